// round 8
// baseline (speedup 1.0000x reference)
#include <cuda_runtime.h>

#define FULLMASK 0xFFFFFFFFu
#define KNN 16
#define GB 256                       // bins per axis
#define NB2 (GB * GB)
#define XLO (-6.0f)
#define BINW (12.0f / 256.0f)
#define BSCALE (256.0f / 12.0f)
#define NCAP 32768
#define RBIG 3.0e38f

// ---- global scratch (no allocation; zero-initialized at module load) ----
// Pipeline is SELF-CLEANING: prefix_kernel re-zeros g_hist after consuming it,
// knn_thread_kernel re-zeros g_cnt after scatter consumed it, so every
// kernel_launch call (and every graph replay) starts from a clean state.
__device__ __align__(16) int g_hist[NB2];
__device__ __align__(16) int g_cnt[NB2];
__device__ __align__(16) int g_binstart[NB2 + 1];
__device__ __align__(16) float2 g_sxy[NCAP];
__device__ int g_sorig[NCAP];

static __device__ __forceinline__ int bin1(float v) {
    int b = (int)((v - XLO) * BSCALE);
    return min(max(b, 0), GB - 1);
}

// ================= setup kernels =================
__global__ void __launch_bounds__(1024, 1)
hist_kernel(const float* __restrict__ p, int n) {
    int i = blockIdx.x * blockDim.x + threadIdx.x;
    if (i < n) {
        float x = p[3 * i];
        float y = p[3 * i + 1];
        atomicAdd(&g_hist[(bin1(y) << 8) | bin1(x)], 1);
    }
}

// exclusive prefix over 65536 bins: 1024 threads x 64 bins each.
// Also re-zeros g_hist (each thread rewrites exactly the bins it read).
__global__ void __launch_bounds__(1024, 1)
prefix_kernel() {
    __shared__ int wsum[32];
    const int tid = threadIdx.x;
    const int lane = tid & 31;
    const int wid = tid >> 5;
    int4* h4 = reinterpret_cast<int4*>(g_hist);

    // pass 1: per-thread sum of 64 bins
    int s = 0;
#pragma unroll
    for (int j = 0; j < 16; j++) {
        int4 v = h4[tid * 16 + j];
        s += v.x + v.y + v.z + v.w;
    }
    int x = s;
#pragma unroll
    for (int d = 1; d < 32; d <<= 1) {
        int y = __shfl_up_sync(FULLMASK, x, d);
        if (lane >= d) x += y;
    }
    if (lane == 31) wsum[wid] = x;
    __syncthreads();
    if (tid < 32) {
        int w = wsum[tid];
#pragma unroll
        for (int d = 1; d < 32; d <<= 1) {
            int y = __shfl_up_sync(FULLMASK, w, d);
            if (tid >= d) w += y;
        }
        wsum[tid] = w;
    }
    __syncthreads();
    // pass 2: re-read, emit exclusive prefix, zero the histogram
    int run = x - s + (wid ? wsum[wid - 1] : 0);
    const int4 z4 = make_int4(0, 0, 0, 0);
#pragma unroll
    for (int j = 0; j < 16; j++) {
        int4 v = h4[tid * 16 + j];
        int4 o;
        o.x = run;
        o.y = run + v.x;
        o.z = run + v.x + v.y;
        o.w = run + v.x + v.y + v.z;
        reinterpret_cast<int4*>(g_binstart)[tid * 16 + j] = o;
        h4[tid * 16 + j] = z4;          // self-clean for next call
        run += v.x + v.y + v.z + v.w;
    }
    if (tid == 1023) g_binstart[NB2] = run;
}

__global__ void __launch_bounds__(1024, 1)
scatter_kernel(const float* __restrict__ p, int n) {
    int i = blockIdx.x * blockDim.x + threadIdx.x;
    if (i < n) {
        float x = p[3 * i];
        float y = p[3 * i + 1];
        int key = (bin1(y) << 8) | bin1(x);
        int pos = g_binstart[key] + atomicAdd(&g_cnt[key], 1);
        g_sxy[pos] = make_float2(x, y);
        g_sorig[pos] = i;
    }
}

// ================= main kernel: one thread per query =================
__global__ void __launch_bounds__(128, 1)
knn_thread_kernel(float* __restrict__ out, int n) {
    const int s = blockIdx.x * blockDim.x + threadIdx.x;

    // self-clean g_cnt for the next replay's scatter (16384 threads x int4
    // covers all 65536 counters)
    {
        int4* c4 = reinterpret_cast<int4*>(g_cnt);
        const int z = blockDim.x * gridDim.x;
        for (int i = s; i < NB2 / 4; i += z) c4[i] = make_int4(0, 0, 0, 0);
    }
    if (s >= n) return;

    const float2 q = __ldg(&g_sxy[s]);
    const float xq = q.x;
    const float yq = q.y;

    // top-16 d^2 list, ascending, in registers
    float kn[KNN];
#pragma unroll
    for (int i = 0; i < KNN; i++) kn[i] = RBIG;
    float kn15 = RBIG;

#define TRY_INSERT(D2)                                                \
    if ((D2) < kn15) {                                                \
        float v = (D2);                                               \
        _Pragma("unroll")                                             \
        for (int i = 0; i < KNN; i++) {                               \
            float lo = fminf(kn[i], v);                               \
            v = fmaxf(kn[i], v);                                      \
            kn[i] = lo;                                               \
        }                                                             \
        kn15 = kn[KNN - 1];                                           \
    }

    // ---- prime: 17 adjacent slots (clamped), excluding self ----
    const int W = min(max(s - 8, 0), n - 17);
#pragma unroll 4
    for (int c = W; c < W + 17; c++) {
        if (c == s) continue;
        float2 v = __ldg(&g_sxy[c]);
        float dx = xq - v.x;
        float dy = yq - v.y;
        float d2 = fmaf(dx, dx, dy * dy);
        TRY_INSERT(d2);
    }

    // ---- radius-pruned grid scan ----
    float rad = sqrtf(kn15);

    auto scan_span = [&](int lo, int hi) {
        for (int c = lo; c < hi; c++) {
            float2 v = __ldg(&g_sxy[c]);
            float dx = xq - v.x;
            float dy = yq - v.y;
            float d2 = fmaf(dx, dx, dy * dy);
            TRY_INSERT(d2);
        }
    };

    auto scan_row = [&](int iy) {
        int bxlo = bin1(xq - rad);
        int bxhi = bin1(xq + rad);
        int base = iy << 8;
        int lo = __ldg(&g_binstart[base + bxlo]);
        int hi = __ldg(&g_binstart[base + bxhi + 1]);
        // skip the already-primed window [W, W+17)
        scan_span(lo, min(hi, W));
        scan_span(max(lo, W + 17), hi);
        rad = sqrtf(kn15);
    };

    const int iyq = bin1(yq);
    scan_row(iyq);
    for (int t = 1;; t++) {
        bool any = false;
        int ru = iyq + t;
        if (ru < GB && yq + rad > XLO + (float)ru * BINW) {
            scan_row(ru);
            any = true;
        }
        int rd = iyq - t;
        if (rd >= 0 && yq - rad < XLO + (float)(rd + 1) * BINW) {
            scan_row(rd);
            any = true;
        }
        if (!any) break;
    }
#undef TRY_INSERT

    // ---- output: sorted distances, scattered to original row ----
    const int orig = __ldg(&g_sorig[s]);
    float4* o = reinterpret_cast<float4*>(out + (size_t)orig * KNN);
    float4 r0, r1, r2, r3;
    r0.x = sqrtf(kn[0]);  r0.y = sqrtf(kn[1]);  r0.z = sqrtf(kn[2]);  r0.w = sqrtf(kn[3]);
    r1.x = sqrtf(kn[4]);  r1.y = sqrtf(kn[5]);  r1.z = sqrtf(kn[6]);  r1.w = sqrtf(kn[7]);
    r2.x = sqrtf(kn[8]);  r2.y = sqrtf(kn[9]);  r2.z = sqrtf(kn[10]); r2.w = sqrtf(kn[11]);
    r3.x = sqrtf(kn[12]); r3.y = sqrtf(kn[13]); r3.z = sqrtf(kn[14]); r3.w = sqrtf(kn[15]);
    o[0] = r0; o[1] = r1; o[2] = r2; o[3] = r3;
}

extern "C" void kernel_launch(void* const* d_in, const int* in_sizes, int n_in,
                              void* d_out, int out_size) {
    const float* p = (const float*)d_in[0];
    float* out = (float*)d_out;
    int n = in_sizes[0] / 3;

    int nb = (n + 1023) / 1024;
    hist_kernel<<<nb, 1024>>>(p, n);
    prefix_kernel<<<1, 1024>>>();
    scatter_kernel<<<nb, 1024>>>(p, n);

    int blocks = (n + 127) / 128;
    knn_thread_kernel<<<blocks, 128>>>(out, n);
}

// round 9
// speedup vs baseline: 1.5210x; 1.5210x over previous
#include <cuda_runtime.h>

#define FULLMASK 0xFFFFFFFFu
#define KNN 16
#define GB 128                       // bins per axis
#define NB2 (GB * GB)                // 16384
#define XLO (-6.0f)
#define BINW (12.0f / 128.0f)        // 0.09375
#define BSCALE (128.0f / 12.0f)
#define NCAP 32768
#define RBIG 3.0e38f

// ---- global scratch (no allocation; zero-initialized at module load) ----
// Self-cleaning pipeline: prefix_kernel re-zeros g_hist, knn2_kernel re-zeros
// g_cnt, so every launch/replay starts clean.
__device__ __align__(16) int g_hist[NB2];
__device__ __align__(16) int g_cnt[NB2];
__device__ __align__(16) int g_binstart[NB2 + 1];
__device__ __align__(16) float2 g_sxy[NCAP];
__device__ int g_sorig[NCAP];

static __device__ __forceinline__ int bin1(float v) {
    int b = (int)((v - XLO) * BSCALE);
    return min(max(b, 0), GB - 1);
}

// ================= setup kernels =================
__global__ void __launch_bounds__(1024, 1)
hist_kernel(const float* __restrict__ p, int n) {
    int i = blockIdx.x * blockDim.x + threadIdx.x;
    if (i < n) {
        float x = p[3 * i];
        float y = p[3 * i + 1];
        atomicAdd(&g_hist[(bin1(y) << 7) | bin1(x)], 1);
    }
}

// exclusive prefix over 16384 bins: 1024 threads x 16 bins each; re-zeros hist
__global__ void __launch_bounds__(1024, 1)
prefix_kernel() {
    __shared__ int wsum[32];
    const int tid = threadIdx.x;
    const int lane = tid & 31;
    const int wid = tid >> 5;
    int4* h4 = reinterpret_cast<int4*>(g_hist);

    int s = 0;
#pragma unroll
    for (int j = 0; j < 4; j++) {
        int4 v = h4[tid * 4 + j];
        s += v.x + v.y + v.z + v.w;
    }
    int x = s;
#pragma unroll
    for (int d = 1; d < 32; d <<= 1) {
        int y = __shfl_up_sync(FULLMASK, x, d);
        if (lane >= d) x += y;
    }
    if (lane == 31) wsum[wid] = x;
    __syncthreads();
    if (tid < 32) {
        int w = wsum[tid];
#pragma unroll
        for (int d = 1; d < 32; d <<= 1) {
            int y = __shfl_up_sync(FULLMASK, w, d);
            if (tid >= d) w += y;
        }
        wsum[tid] = w;
    }
    __syncthreads();
    int run = x - s + (wid ? wsum[wid - 1] : 0);
    const int4 z4 = make_int4(0, 0, 0, 0);
#pragma unroll
    for (int j = 0; j < 4; j++) {
        int4 v = h4[tid * 4 + j];
        int4 o;
        o.x = run;
        o.y = run + v.x;
        o.z = run + v.x + v.y;
        o.w = run + v.x + v.y + v.z;
        reinterpret_cast<int4*>(g_binstart)[tid * 4 + j] = o;
        h4[tid * 4 + j] = z4;           // self-clean
        run += v.x + v.y + v.z + v.w;
    }
    if (tid == 1023) g_binstart[NB2] = run;
}

__global__ void __launch_bounds__(1024, 1)
scatter_kernel(const float* __restrict__ p, int n) {
    int i = blockIdx.x * blockDim.x + threadIdx.x;
    if (i < n) {
        float x = p[3 * i];
        float y = p[3 * i + 1];
        int key = (bin1(y) << 7) | bin1(x);
        int pos = g_binstart[key] + atomicAdd(&g_cnt[key], 1);
        g_sxy[pos] = make_float2(x, y);
        g_sorig[pos] = i;
    }
}

// ================= main kernel: TWO threads per query =================
__global__ void __launch_bounds__(128, 1)
knn2_kernel(float* __restrict__ out, int n) {
    const int t = blockIdx.x * blockDim.x + threadIdx.x;

    // self-clean g_cnt for next replay (4096 int4s; >=4096 threads exist)
    if (t < NB2 / 4) reinterpret_cast<int4*>(g_cnt)[t] = make_int4(0, 0, 0, 0);

    const int s = t >> 1;          // query slot
    const int sub = t & 1;         // pair member
    if (s >= n) return;
    const unsigned pmask = 3u << (threadIdx.x & 30);

    const float2 q = __ldg(&g_sxy[s]);
    const float xq = q.x;
    const float yq = q.y;

    // ---- prime: window of 32 slots, 16 per thread, unsorted fill ----
    const int W = min(max(s - 16, 0), n - 32);
    float kn[KNN];
#pragma unroll
    for (int j = 0; j < KNN; j++) {
        int c = W + 2 * j + sub;
        float2 v = __ldg(&g_sxy[c]);
        float dx = xq - v.x;
        float dy = yq - v.y;
        float d2 = fmaf(dx, dx, dy * dy);
        kn[j] = (c == s) ? RBIG : d2;
    }
    // full bitonic sort of 16 registers (static network)
#pragma unroll
    for (int k = 2; k <= 16; k <<= 1) {
#pragma unroll
        for (int j = k >> 1; j > 0; j >>= 1) {
#pragma unroll
            for (int i = 0; i < 16; i++) {
                int l = i ^ j;
                if (l > i) {
                    bool up = ((i & k) == 0);
                    float mn = fminf(kn[i], kn[l]);
                    float mx = fmaxf(kn[i], kn[l]);
                    kn[i] = up ? mn : mx;
                    kn[l] = up ? mx : mn;
                }
            }
        }
    }
    float kn15 = kn[KNN - 1];

#define TRY_INSERT(D2)                                                \
    if ((D2) < kn15) {                                                \
        float v = (D2);                                               \
        _Pragma("unroll")                                             \
        for (int i = 0; i < KNN; i++) {                               \
            float lo = fminf(kn[i], v);                               \
            v = fmaxf(kn[i], v);                                      \
            kn[i] = lo;                                               \
        }                                                             \
        kn15 = kn[KNN - 1];                                           \
    }

    // group threshold (min of pair's upper bounds is a valid upper bound)
    float kng = fminf(kn15, __shfl_xor_sync(pmask, kn15, 1));
    float rad = sqrtf(kng) * 1.0001f;

    // pair-partitioned span scan (stride 2), window [W, W+32) skipped
    auto scan_span = [&](int lo, int hi) {
        for (int c = lo + sub; c < hi; c += 2) {
            float2 v = __ldg(&g_sxy[c]);
            float dx = xq - v.x;
            float dy = yq - v.y;
            float d2 = fmaf(dx, dx, dy * dy);
            TRY_INSERT(d2);
        }
    };

    auto scan_row = [&](int iy) {
        int bxlo = bin1(xq - rad);
        int bxhi = bin1(xq + rad);
        int base = iy << 7;
        int lo = __ldg(&g_binstart[base + bxlo]);
        int hi = __ldg(&g_binstart[base + bxhi + 1]);
        scan_span(lo, min(hi, W));
        scan_span(max(lo, W + 32), hi);
        kng = fminf(kn15, __shfl_xor_sync(pmask, kn15, 1));
        rad = sqrtf(kng) * 1.0001f;
    };

    const int iyq = bin1(yq);
    scan_row(iyq);
    for (int tt = 1;; tt++) {
        bool any = false;
        int ru = iyq + tt;
        if (ru < GB && yq + rad > XLO + (float)ru * BINW) {
            scan_row(ru);
            any = true;
        }
        int rd = iyq - tt;
        if (rd >= 0 && yq - rad < XLO + (float)(rd + 1) * BINW) {
            scan_row(rd);
            any = true;
        }
        if (!any) break;
    }
#undef TRY_INSERT

    // ---- merge pair's sorted lists: union top-16 ----
    float m[KNN];
#pragma unroll
    for (int i = 0; i < KNN; i++) {
        float b = __shfl_xor_sync(pmask, kn[KNN - 1 - i], 1);
        m[i] = fminf(kn[i], b);       // bitonic sequence of union's 16 smallest
    }
#pragma unroll
    for (int j = 8; j > 0; j >>= 1) {
#pragma unroll
        for (int i = 0; i < 16; i++) {
            if (!(i & j)) {
                float mn = fminf(m[i], m[i | j]);
                float mx = fmaxf(m[i], m[i | j]);
                m[i] = mn;
                m[i | j] = mx;
            }
        }
    }

    // ---- output (one writer per query): sorted distances to original row ----
    if (sub == 0) {
        const int orig = __ldg(&g_sorig[s]);
        float4* o = reinterpret_cast<float4*>(out + (size_t)orig * KNN);
        float4 r0, r1, r2, r3;
        r0.x = sqrtf(m[0]);  r0.y = sqrtf(m[1]);  r0.z = sqrtf(m[2]);  r0.w = sqrtf(m[3]);
        r1.x = sqrtf(m[4]);  r1.y = sqrtf(m[5]);  r1.z = sqrtf(m[6]);  r1.w = sqrtf(m[7]);
        r2.x = sqrtf(m[8]);  r2.y = sqrtf(m[9]);  r2.z = sqrtf(m[10]); r2.w = sqrtf(m[11]);
        r3.x = sqrtf(m[12]); r3.y = sqrtf(m[13]); r3.z = sqrtf(m[14]); r3.w = sqrtf(m[15]);
        o[0] = r0; o[1] = r1; o[2] = r2; o[3] = r3;
    }
}

extern "C" void kernel_launch(void* const* d_in, const int* in_sizes, int n_in,
                              void* d_out, int out_size) {
    const float* p = (const float*)d_in[0];
    float* out = (float*)d_out;
    int n = in_sizes[0] / 3;

    int nb = (n + 1023) / 1024;
    hist_kernel<<<nb, 1024>>>(p, n);
    prefix_kernel<<<1, 1024>>>();
    scatter_kernel<<<nb, 1024>>>(p, n);

    int threads = 2 * n;
    int blocks = (threads + 127) / 128;
    knn2_kernel<<<blocks, 128>>>(out, n);
}

// round 10
// speedup vs baseline: 1.9776x; 1.3002x over previous
#include <cuda_runtime.h>

#define FULLMASK 0xFFFFFFFFu
#define KNN 16
#define GB 128                       // bins per axis
#define NB2 (GB * GB)                // 16384
#define XLO (-6.0f)
#define BINW (12.0f / 128.0f)
#define BSCALE (128.0f / 12.0f)
#define NCAP 32768
#define RBIG 3.0e38f
#define TPQ 4                        // threads per query

// ---- global scratch (no allocation; zero-initialized at module load) ----
// Self-cleaning: prefix_kernel re-zeros g_hist, knn4_kernel re-zeros g_cnt.
__device__ __align__(16) int g_hist[NB2];
__device__ __align__(16) int g_cnt[NB2];
__device__ __align__(16) int g_binstart[NB2 + 1];
__device__ __align__(16) float2 g_sxy[NCAP];
__device__ int g_sorig[NCAP];

static __device__ __forceinline__ int bin1(float v) {
    int b = (int)((v - XLO) * BSCALE);
    return min(max(b, 0), GB - 1);
}

// ================= setup kernels =================
__global__ void __launch_bounds__(1024, 1)
hist_kernel(const float* __restrict__ p, int n) {
    int i = blockIdx.x * blockDim.x + threadIdx.x;
    if (i < n) {
        float x = p[3 * i];
        float y = p[3 * i + 1];
        atomicAdd(&g_hist[(bin1(y) << 7) | bin1(x)], 1);
    }
}

// exclusive prefix over 16384 bins: 1024 threads x 16 bins each; re-zeros hist
__global__ void __launch_bounds__(1024, 1)
prefix_kernel() {
    __shared__ int wsum[32];
    const int tid = threadIdx.x;
    const int lane = tid & 31;
    const int wid = tid >> 5;
    int4* h4 = reinterpret_cast<int4*>(g_hist);

    int s = 0;
#pragma unroll
    for (int j = 0; j < 4; j++) {
        int4 v = h4[tid * 4 + j];
        s += v.x + v.y + v.z + v.w;
    }
    int x = s;
#pragma unroll
    for (int d = 1; d < 32; d <<= 1) {
        int y = __shfl_up_sync(FULLMASK, x, d);
        if (lane >= d) x += y;
    }
    if (lane == 31) wsum[wid] = x;
    __syncthreads();
    if (tid < 32) {
        int w = wsum[tid];
#pragma unroll
        for (int d = 1; d < 32; d <<= 1) {
            int y = __shfl_up_sync(FULLMASK, w, d);
            if (tid >= d) w += y;
        }
        wsum[tid] = w;
    }
    __syncthreads();
    int run = x - s + (wid ? wsum[wid - 1] : 0);
    const int4 z4 = make_int4(0, 0, 0, 0);
#pragma unroll
    for (int j = 0; j < 4; j++) {
        int4 v = h4[tid * 4 + j];
        int4 o;
        o.x = run;
        o.y = run + v.x;
        o.z = run + v.x + v.y;
        o.w = run + v.x + v.y + v.z;
        reinterpret_cast<int4*>(g_binstart)[tid * 4 + j] = o;
        h4[tid * 4 + j] = z4;           // self-clean
        run += v.x + v.y + v.z + v.w;
    }
    if (tid == 1023) g_binstart[NB2] = run;
}

__global__ void __launch_bounds__(1024, 1)
scatter_kernel(const float* __restrict__ p, int n) {
    int i = blockIdx.x * blockDim.x + threadIdx.x;
    if (i < n) {
        float x = p[3 * i];
        float y = p[3 * i + 1];
        int key = (bin1(y) << 7) | bin1(x);
        int pos = g_binstart[key] + atomicAdd(&g_cnt[key], 1);
        g_sxy[pos] = make_float2(x, y);
        g_sorig[pos] = i;
    }
}

// ================= main kernel: FOUR threads per query =================
__global__ void __launch_bounds__(128, 1)
knn4_kernel(float* __restrict__ out, int n) {
    const int t = blockIdx.x * blockDim.x + threadIdx.x;

    // self-clean g_cnt for next replay (4096 int4s; plenty of threads)
    if (t < NB2 / 4) reinterpret_cast<int4*>(g_cnt)[t] = make_int4(0, 0, 0, 0);

    const int s = t >> 2;          // query slot
    const int sub = t & 3;         // group member 0..3
    if (s >= n) return;
    const unsigned gmask = 0xFu << (threadIdx.x & 28);

    const float2 q = __ldg(&g_sxy[s]);
    const float xq = q.x;
    const float yq = q.y;

    // ---- prime: window of 64 slots, 16 per thread (stride 4) ----
    const int W = min(max(s - 32, 0), n - 64);
    float kn[KNN];
#pragma unroll
    for (int j = 0; j < KNN; j++) {
        int c = W + 4 * j + sub;
        float2 v = __ldg(&g_sxy[c]);
        float dx = xq - v.x;
        float dy = yq - v.y;
        float d2 = fmaf(dx, dx, dy * dy);
        kn[j] = (c == s) ? RBIG : d2;
    }
    // full bitonic sort of 16 registers (static network)
#pragma unroll
    for (int k = 2; k <= 16; k <<= 1) {
#pragma unroll
        for (int j = k >> 1; j > 0; j >>= 1) {
#pragma unroll
            for (int i = 0; i < 16; i++) {
                int l = i ^ j;
                if (l > i) {
                    bool up = ((i & k) == 0);
                    float mn = fminf(kn[i], kn[l]);
                    float mx = fmaxf(kn[i], kn[l]);
                    kn[i] = up ? mn : mx;
                    kn[l] = up ? mx : mn;
                }
            }
        }
    }
    float kn15 = kn[KNN - 1];

#define TRY_INSERT(D2)                                                \
    if ((D2) < kn15) {                                                \
        float v = (D2);                                               \
        _Pragma("unroll")                                             \
        for (int i = 0; i < KNN; i++) {                               \
            float lo = fminf(kn[i], v);                               \
            v = fmaxf(kn[i], v);                                      \
            kn[i] = lo;                                               \
        }                                                             \
        kn15 = kn[KNN - 1];                                           \
    }

    // group threshold: min of the 4 per-thread 16th-best upper bounds
    float kng = fminf(kn15, __shfl_xor_sync(gmask, kn15, 1));
    kng = fminf(kng, __shfl_xor_sync(gmask, kng, 2));
    float rad = sqrtf(kng) * 1.0001f;

    // group-partitioned span scan (stride 4), MLP=2; window [W, W+64) skipped
    auto scan_span = [&](int lo, int hi) {
        int c = lo + sub;
        for (; c + 4 < hi; c += 8) {
            float2 v0 = __ldg(&g_sxy[c]);
            float2 v1 = __ldg(&g_sxy[c + 4]);
            float dx0 = xq - v0.x, dy0 = yq - v0.y;
            float dx1 = xq - v1.x, dy1 = yq - v1.y;
            float d20 = fmaf(dx0, dx0, dy0 * dy0);
            float d21 = fmaf(dx1, dx1, dy1 * dy1);
            TRY_INSERT(d20);
            TRY_INSERT(d21);
        }
        if (c < hi) {
            float2 v = __ldg(&g_sxy[c]);
            float dx = xq - v.x, dy = yq - v.y;
            float d2 = fmaf(dx, dx, dy * dy);
            TRY_INSERT(d2);
        }
    };

    auto scan_row = [&](int iy) {
        int bxlo = bin1(xq - rad);
        int bxhi = bin1(xq + rad);
        int base = iy << 7;
        int lo = __ldg(&g_binstart[base + bxlo]);
        int hi = __ldg(&g_binstart[base + bxhi + 1]);
        scan_span(lo, min(hi, W));
        scan_span(max(lo, W + 64), hi);
        kng = fminf(kn15, __shfl_xor_sync(gmask, kn15, 1));
        kng = fminf(kng, __shfl_xor_sync(gmask, kng, 2));
        rad = sqrtf(kng) * 1.0001f;
    };

    const int iyq = bin1(yq);
    scan_row(iyq);
    for (int tt = 1;; tt++) {
        bool any = false;
        int ru = iyq + tt;
        if (ru < GB && yq + rad > XLO + (float)ru * BINW) {
            scan_row(ru);
            any = true;
        }
        int rd = iyq - tt;
        if (rd >= 0 && yq - rad < XLO + (float)(rd + 1) * BINW) {
            scan_row(rd);
            any = true;
        }
        if (!any) break;
    }
#undef TRY_INSERT

    // ---- merge the group's four sorted lists into union top-16 ----
#pragma unroll
    for (int step = 1; step <= 2; step <<= 1) {
        float m[KNN];
#pragma unroll
        for (int i = 0; i < KNN; i++) {
            float b = __shfl_xor_sync(gmask, kn[KNN - 1 - i], step);
            m[i] = fminf(kn[i], b);   // bitonic sequence of union's 16 smallest
        }
#pragma unroll
        for (int j = 8; j > 0; j >>= 1) {
#pragma unroll
            for (int i = 0; i < 16; i++) {
                if (!(i & j)) {
                    float mn = fminf(m[i], m[i | j]);
                    float mx = fmaxf(m[i], m[i | j]);
                    m[i] = mn;
                    m[i | j] = mx;
                }
            }
        }
#pragma unroll
        for (int i = 0; i < KNN; i++) kn[i] = m[i];
    }

    // ---- output (one writer per query): sorted distances to original row ----
    if (sub == 0) {
        const int orig = __ldg(&g_sorig[s]);
        float4* o = reinterpret_cast<float4*>(out + (size_t)orig * KNN);
        float4 r0, r1, r2, r3;
        r0.x = sqrtf(kn[0]);  r0.y = sqrtf(kn[1]);  r0.z = sqrtf(kn[2]);  r0.w = sqrtf(kn[3]);
        r1.x = sqrtf(kn[4]);  r1.y = sqrtf(kn[5]);  r1.z = sqrtf(kn[6]);  r1.w = sqrtf(kn[7]);
        r2.x = sqrtf(kn[8]);  r2.y = sqrtf(kn[9]);  r2.z = sqrtf(kn[10]); r2.w = sqrtf(kn[11]);
        r3.x = sqrtf(kn[12]); r3.y = sqrtf(kn[13]); r3.z = sqrtf(kn[14]); r3.w = sqrtf(kn[15]);
        o[0] = r0; o[1] = r1; o[2] = r2; o[3] = r3;
    }
}

extern "C" void kernel_launch(void* const* d_in, const int* in_sizes, int n_in,
                              void* d_out, int out_size) {
    const float* p = (const float*)d_in[0];
    float* out = (float*)d_out;
    int n = in_sizes[0] / 3;

    int nb = (n + 1023) / 1024;
    hist_kernel<<<nb, 1024>>>(p, n);
    prefix_kernel<<<1, 1024>>>();
    scatter_kernel<<<nb, 1024>>>(p, n);

    int threads = TPQ * n;
    int blocks = (threads + 127) / 128;
    knn4_kernel<<<blocks, 128>>>(out, n);
}